// round 1
// baseline (speedup 1.0000x reference)
#include <cuda_runtime.h>
#include <math.h>

#define B_  2048
#define K_  16
#define M_  16
#define D_  256
#define NITER  20
#define MESHIT 3

// Scratch (allocation-free: __device__ globals)
__device__ float g_H [B_ * K_ * D_];   // hidden layer, reused for q and r
__device__ float g_Pq[B_ * K_ * D_];   // projected q
__device__ float g_Pr[B_ * M_ * D_];   // projected r

// ---------------------------------------------------------------------------
// GEMM: Y[row][col] = sum_d A[row][d] * W[col][d] + bias[col]   (x @ W.T + b)
// Tile 128x128, BK=16, 256 threads, 8x8 per thread. N = K = 256 fixed.
// ---------------------------------------------------------------------------
template <int RELU>
__global__ void __launch_bounds__(256) mlp_gemm_kernel(
    const float* __restrict__ A, const float* __restrict__ W,
    const float* __restrict__ bias, float* __restrict__ Y)
{
    __shared__ float As[16][132];   // [k][m], padded vs bank conflicts
    __shared__ float Bs[16][132];   // [k][n]

    const int tid  = threadIdx.x;
    const int tx   = tid & 15;      // n-tile
    const int ty   = tid >> 4;      // m-tile
    const int row0 = blockIdx.x * 128;
    const int col0 = blockIdx.y * 128;

    float acc[8][8];
#pragma unroll
    for (int i = 0; i < 8; i++)
#pragma unroll
        for (int j = 0; j < 8; j++) acc[i][j] = 0.f;

    for (int k0 = 0; k0 < D_; k0 += 16) {
#pragma unroll
        for (int t = 0; t < 2; t++) {
            int idx4 = tid + t * 256;        // 0..511 float4 slots
            int r    = idx4 >> 2;            // 0..127 row within tile
            int c    = (idx4 & 3) << 2;      // 0,4,8,12 k-offset
            float4 va = *reinterpret_cast<const float4*>(
                A + (size_t)(row0 + r) * D_ + k0 + c);
            As[c + 0][r] = va.x; As[c + 1][r] = va.y;
            As[c + 2][r] = va.z; As[c + 3][r] = va.w;
            float4 vb = *reinterpret_cast<const float4*>(
                W + (size_t)(col0 + r) * D_ + k0 + c);
            Bs[c + 0][r] = vb.x; Bs[c + 1][r] = vb.y;
            Bs[c + 2][r] = vb.z; Bs[c + 3][r] = vb.w;
        }
        __syncthreads();
#pragma unroll
        for (int kk = 0; kk < 16; kk++) {
            float a[8], bb[8];
#pragma unroll
            for (int i = 0; i < 8; i++) a[i]  = As[kk][ty * 8 + i];
#pragma unroll
            for (int j = 0; j < 8; j++) bb[j] = Bs[kk][tx * 8 + j];
#pragma unroll
            for (int i = 0; i < 8; i++)
#pragma unroll
                for (int j = 0; j < 8; j++)
                    acc[i][j] = fmaf(a[i], bb[j], acc[i][j]);
        }
        __syncthreads();
    }

    float bj[8];
#pragma unroll
    for (int j = 0; j < 8; j++) bj[j] = bias[col0 + tx * 8 + j];

#pragma unroll
    for (int i = 0; i < 8; i++) {
        int row = row0 + ty * 8 + i;
        float v[8];
#pragma unroll
        for (int j = 0; j < 8; j++) {
            float x = acc[i][j] + bj[j];
            if (RELU) x = fmaxf(x, 0.f);
            v[j] = x;
        }
        float* yp = Y + (size_t)row * D_ + col0 + tx * 8;
        *reinterpret_cast<float4*>(yp)     = make_float4(v[0], v[1], v[2], v[3]);
        *reinterpret_cast<float4*>(yp + 4) = make_float4(v[4], v[5], v[6], v[7]);
    }
}

// ---------------------------------------------------------------------------
// Per-batch fused kernel: pairwise cost C, Sinkhorn (log domain, 20 it),
// MESH (3 it), transport cost, sigmoid. One CTA per batch, thread = (k,m).
// ---------------------------------------------------------------------------
__global__ void __launch_bounds__(256) sinkhorn_kernel(
    const float* __restrict__ Pq, const float* __restrict__ Pr,
    const float* __restrict__ mask_q, const float* __restrict__ mask_r,
    float* __restrict__ out_sim, float* __restrict__ out_T,
    float* __restrict__ out_C,   float* __restrict__ out_cost)
{
    const int b   = blockIdx.x;
    const int tid = threadIdx.x;
    const int k   = tid >> 4;   // 0..15
    const int m   = tid & 15;   // 0..15

    __shared__ float sq[16][257];   // +1 pad -> conflict-free column reads
    __shared__ float sr[16][257];
    __shared__ float st[16 * 17];   // transpose staging
    __shared__ float sb[16];
    __shared__ float slmq[16], slmr[16];
    __shared__ float red[8];

    const float* pq = Pq + (size_t)b * K_ * D_;
    const float* pr = Pr + (size_t)b * M_ * D_;
    for (int idx = tid; idx < K_ * D_; idx += 256) {
        sq[idx >> 8][idx & 255] = pq[idx];
        sr[idx >> 8][idx & 255] = pr[idx];
    }
    if (tid < 16) {
        slmq[tid] = logf(fmaxf(mask_q[b * K_ + tid], 1e-8f));
        slmr[tid] = logf(fmaxf(mask_r[b * M_ + tid], 1e-8f));
    }
    __syncthreads();

    // ---- cost C[k][m] = sqrt(clip(sum_d (q-r)^2, 1e-6)) ----
    float c = 0.f;
#pragma unroll 8
    for (int d = 0; d < D_; d++) {
        float df = sq[k][d] - sr[m][d];
        c = fmaf(df, df, c);
    }
    const float Cv = sqrtf(fmaxf(c, 1e-6f));

    // ---- normalized log marginals (redundant per-thread, 16 entries) ----
    float mxq = -INFINITY, mxr = -INFINITY;
#pragma unroll
    for (int i = 0; i < 16; i++) { mxq = fmaxf(mxq, slmq[i]); mxr = fmaxf(mxr, slmr[i]); }
    float sqs = 0.f, srs = 0.f;
#pragma unroll
    for (int i = 0; i < 16; i++) { sqs += expf(slmq[i] - mxq); srs += expf(slmr[i] - mxr); }
    const float log_mu = slmq[k] - (mxq + logf(sqs));
    const float log_nu = slmr[m] - (mxr + logf(srs));

    const float lK = -Cv / 0.05f + log_mu + log_nu;

    // ---- Sinkhorn, log domain ----
    float alpha = 0.f, beta = 0.f;
    for (int it = 0; it < NITER; it++) {
        // alpha_k = -lse_m(lK + beta_m): reduce over 16-lane group
        float v  = lK + beta;
        float mx = v;
        mx = fmaxf(mx, __shfl_xor_sync(0xffffffffu, mx, 1));
        mx = fmaxf(mx, __shfl_xor_sync(0xffffffffu, mx, 2));
        mx = fmaxf(mx, __shfl_xor_sync(0xffffffffu, mx, 4));
        mx = fmaxf(mx, __shfl_xor_sync(0xffffffffu, mx, 8));
        float s = expf(v - mx);
        s += __shfl_xor_sync(0xffffffffu, s, 1);
        s += __shfl_xor_sync(0xffffffffu, s, 2);
        s += __shfl_xor_sync(0xffffffffu, s, 4);
        s += __shfl_xor_sync(0xffffffffu, s, 8);
        alpha = -(mx + logf(s));

        // beta_m = -lse_k(lK + alpha_k): smem transpose, then lane reduce
        st[m * 17 + k] = lK + alpha;
        __syncthreads();
        float u  = st[k * 17 + m];   // transposed element
        float mu = u;
        mu = fmaxf(mu, __shfl_xor_sync(0xffffffffu, mu, 1));
        mu = fmaxf(mu, __shfl_xor_sync(0xffffffffu, mu, 2));
        mu = fmaxf(mu, __shfl_xor_sync(0xffffffffu, mu, 4));
        mu = fmaxf(mu, __shfl_xor_sync(0xffffffffu, mu, 8));
        float su = expf(u - mu);
        su += __shfl_xor_sync(0xffffffffu, su, 1);
        su += __shfl_xor_sync(0xffffffffu, su, 2);
        su += __shfl_xor_sync(0xffffffffu, su, 4);
        su += __shfl_xor_sync(0xffffffffu, su, 8);
        if (m == 0) sb[k] = -(mu + logf(su));
        __syncthreads();
        beta = sb[m];
    }

    float T = expf(lK + alpha + beta);

    // ---- MESH power sharpening ----
    for (int it = 0; it < MESHIT; it++) {
        T = T * T;
        float rs = T;
        rs += __shfl_xor_sync(0xffffffffu, rs, 1);
        rs += __shfl_xor_sync(0xffffffffu, rs, 2);
        rs += __shfl_xor_sync(0xffffffffu, rs, 4);
        rs += __shfl_xor_sync(0xffffffffu, rs, 8);
        T = T / (rs + 1e-8f);

        st[m * 17 + k] = T;
        __syncthreads();
        float u  = st[k * 17 + m];
        float cs = u;
        cs += __shfl_xor_sync(0xffffffffu, cs, 1);
        cs += __shfl_xor_sync(0xffffffffu, cs, 2);
        cs += __shfl_xor_sync(0xffffffffu, cs, 4);
        cs += __shfl_xor_sync(0xffffffffu, cs, 8);
        if (m == 0) sb[k] = cs;
        __syncthreads();
        T = T / (sb[m] + 1e-8f);
    }

    // ---- transport cost + sigmoid ----
    float tc = T * Cv;
    tc += __shfl_xor_sync(0xffffffffu, tc, 16);
    tc += __shfl_xor_sync(0xffffffffu, tc, 8);
    tc += __shfl_xor_sync(0xffffffffu, tc, 4);
    tc += __shfl_xor_sync(0xffffffffu, tc, 2);
    tc += __shfl_xor_sync(0xffffffffu, tc, 1);
    if ((tid & 31) == 0) red[tid >> 5] = tc;
    __syncthreads();
    if (tid == 0) {
        float s = 0.f;
#pragma unroll
        for (int i = 0; i < 8; i++) s += red[i];
        out_cost[b] = s;
        out_sim[b]  = 1.f / (1.f + expf(s));
    }

    out_T[(size_t)b * 256 + tid] = T;
    out_C[(size_t)b * 256 + tid] = Cv;
}

// ---------------------------------------------------------------------------
extern "C" void kernel_launch(void* const* d_in, const int* in_sizes, int n_in,
                              void* d_out, int out_size)
{
    const float* slots_q = (const float*)d_in[0];
    const float* slots_r = (const float*)d_in[1];
    const float* mask_q  = (const float*)d_in[2];
    const float* mask_r  = (const float*)d_in[3];
    const float* W1      = (const float*)d_in[4];
    const float* b1      = (const float*)d_in[5];
    const float* W2      = (const float*)d_in[6];
    const float* b2      = (const float*)d_in[7];

    float* out      = (float*)d_out;
    float* out_sim  = out;                       // [B]
    float* out_T    = out_sim + B_;              // [B,K,M]
    float* out_C    = out_T + (size_t)B_ * K_ * M_;  // [B,K,M]
    float* out_cost = out_C + (size_t)B_ * K_ * M_;  // [B]

    float *pH, *pPq, *pPr;
    cudaGetSymbolAddress((void**)&pH,  g_H);
    cudaGetSymbolAddress((void**)&pPq, g_Pq);
    cudaGetSymbolAddress((void**)&pPr, g_Pr);

    dim3 grid(B_ * K_ / 128, D_ / 128);   // (256, 2)
    dim3 blk(256);

    mlp_gemm_kernel<1><<<grid, blk>>>(slots_q, W1, b1, pH);
    mlp_gemm_kernel<0><<<grid, blk>>>(pH,      W2, b2, pPq);
    mlp_gemm_kernel<1><<<grid, blk>>>(slots_r, W1, b1, pH);
    mlp_gemm_kernel<0><<<grid, blk>>>(pH,      W2, b2, pPr);

    sinkhorn_kernel<<<B_, 256>>>(pPq, pPr, mask_q, mask_r,
                                 out_sim, out_T, out_C, out_cost);
}